// round 15
// baseline (speedup 1.0000x reference)
#include <cuda_runtime.h>
#include <cuda_fp16.h>
#include <cstdint>

#define OUTF 11008
#define INF  4096
#define ROWS 16                        // rows per CTA (shared by all 4 warps)
#define KCTA 512                       // cols per CTA; each warp owns 128
#define NROWT (OUTF / ROWS)            // 688
#define NKC   (INF / KCTA)             // 8

// x pre-split to fp16 hi/lo, layout [k2][batch] as half2-in-unsigned.
__device__ __align__(16) unsigned g_XH[(INF / 2) * 8];
__device__ __align__(16) unsigned g_XL[(INF / 2) * 8];

// Fused: zero the output AND split x into fp16 hi/lo slabs.
__global__ void prep_zero(const float* __restrict__ x, float4* __restrict__ out4, int nout4) {
    int i = blockIdx.x * blockDim.x + threadIdx.x;
    if (i < (INF / 2) * 8) {
        int k2 = i >> 3, n = i & 7;
        float f0 = x[n * INF + 2 * k2];
        float f1 = x[n * INF + 2 * k2 + 1];
        __half h0 = __float2half_rn(f0), h1 = __float2half_rn(f1);
        __half l0 = __float2half_rn(f0 - __half2float(h0));
        __half l1 = __float2half_rn(f1 - __half2float(h1));
        __half2 H = __halves2half2(h0, h1), L = __halves2half2(l0, l1);
        g_XH[i] = *reinterpret_cast<unsigned*>(&H);
        g_XL[i] = *reinterpret_cast<unsigned*>(&L);
    }
    if (i < nout4) out4[i] = make_float4(0.f, 0.f, 0.f, 0.f);
}

// Dequant one packed byte -> half2 (n_lo-8, n_hi-8), exact (Sterbenz).
__device__ __forceinline__ unsigned dq(unsigned v) {
    unsigned t = ((v | (v << 12)) & 0x000F000Fu) | 0x64006400u;  // fp16 (1024+n)
    unsigned c = 0xE408E408u;                                    // half2(-1032)
    __half2 h = __hadd2(*reinterpret_cast<__half2*>(&t),
                        *reinterpret_cast<__half2*>(&c));
    return *reinterpret_cast<unsigned*>(&h);
}

__device__ __forceinline__ void mma16816(float& d0, float& d1, float& d2, float& d3,
                                         unsigned a0, unsigned a1, unsigned a2, unsigned a3,
                                         unsigned b0, unsigned b1) {
    asm volatile(
        "mma.sync.aligned.m16n8k16.row.col.f32.f16.f16.f32 "
        "{%0,%1,%2,%3},{%4,%5,%6,%7},{%8,%9},{%0,%1,%2,%3};"
        : "+f"(d0), "+f"(d1), "+f"(d2), "+f"(d3)
        : "r"(a0), "r"(a1), "r"(a2), "r"(a3), "r"(b0), "r"(b1));
}

__device__ __forceinline__ void cpa16(void* smem, const void* gmem) {
    unsigned s = (unsigned)__cvta_generic_to_shared(smem);
    asm volatile("cp.async.cg.shared.global [%0], [%1], 16;" :: "r"(s), "l"(gmem));
}

__global__ __launch_bounds__(128, 6)
void qlin_kernel(const int*   __restrict__ packed,
                 const float* __restrict__ scales,
                 float*       __restrict__ out) {
    // Per-warp private regions; warps never touch each other's data -> NO CTA syncs.
    __shared__ __align__(16) unsigned Wsm[4][ROWS * 68];   // 4 x 4352 B (stride 68: banks 4*gid+tg bijective)
    __shared__ __align__(16) unsigned xhs[4][64 * 8];      // 4 x 2048 B
    __shared__ __align__(16) unsigned xls[4][64 * 8];      // 4 x 2048 B
    __shared__ __align__(16) float    ssm[4][ROWS * 5];    // 4 x 320 B (stride 5)

    const int tid  = threadIdx.x;
    const int lane = tid & 31, w = tid >> 5;
    const int gid  = lane >> 2, tg = lane & 3;
    const int rowbase = blockIdx.x * ROWS;
    const int kbase   = blockIdx.y * KCTA;
    const int kw2     = (kbase >> 1) + 64 * w;      // this warp's word offset in a row

    const int* pg = packed + (size_t)rowbase * (INF / 2) + kw2;

    // ── Group 0: x slabs (this warp's 128 cols) + W word-half 0..7 (blocks 0,1).
    {
        const int4* gh = reinterpret_cast<const int4*>(g_XH + kw2 * 8);
        const int4* gl = reinterpret_cast<const int4*>(g_XL + kw2 * 8);
        int4* xh4 = reinterpret_cast<int4*>(xhs[w]);
        int4* xl4 = reinterpret_cast<int4*>(xls[w]);
        #pragma unroll
        for (int p = 0; p < 4; p++) {               // 128 int4 per slab, 4/lane
            cpa16(xh4 + p * 32 + lane, gh + p * 32 + lane);
            cpa16(xl4 + p * 32 + lane, gl + p * 32 + lane);
        }
        #pragma unroll
        for (int p = 0; p < 4; p++) {               // 16 rows x 8 int4, 4/lane
            int idx = p * 32 + lane;
            int row = idx >> 3, q = idx & 7;
            cpa16(&Wsm[w][row * 68 + q * 4], pg + (size_t)row * (INF / 2) + q * 4);
        }
    }
    asm volatile("cp.async.commit_group;" ::: "memory");
    // ── Group 1: W word-half 8..15 (blocks 2,3).
    {
        #pragma unroll
        for (int p = 0; p < 4; p++) {
            int idx = p * 32 + lane;
            int row = idx >> 3, q = idx & 7;
            cpa16(&Wsm[w][row * 68 + (q + 8) * 4],
                  pg + (size_t)row * (INF / 2) + (q + 8) * 4);
        }
    }
    asm volatile("cp.async.commit_group;" ::: "memory");

    // ── Scales: this warp's 4 blocks for 16 rows; plain LDG.128 + scalar STS
    // (stride-5 smem is not 16B aligned). Latency overlaps the cp.async drain.
    if (lane < ROWS) {
        const float* sg = scales + (size_t)(rowbase + lane) * (INF / 32) + (kbase >> 5) + 4 * w;
        float4 a = *reinterpret_cast<const float4*>(sg);
        float* d = &ssm[w][lane * 5];
        d[0] = a.x; d[1] = a.y; d[2] = a.z; d[3] = a.w;
    }
    __syncwarp();

    const unsigned* wr0 = &Wsm[w][gid * 68];        // rows gid and gid+8
    const unsigned* wr8 = wr0 + 8 * 68;

    float acc0 = 0.f, acc1 = 0.f, acc2 = 0.f, acc3 = 0.f;

    #pragma unroll
    for (int half = 0; half < 2; half++) {
        if (half == 0)
            asm volatile("cp.async.wait_group 1;" ::: "memory");
        else
            asm volatile("cp.async.wait_group 0;" ::: "memory");
        __syncwarp();                               // own-warp data only: no bar.sync

        #pragma unroll
        for (int bb = 0; bb < 2; bb++) {            // q4 block = 32 cols = 2 k-tiles
            const int blk = half * 2 + bb;
            float t0 = 0.f, t1 = 0.f, t2 = 0.f, t3 = 0.f;
            #pragma unroll
            for (int u = 0; u < 2; u++) {
                const int t = blk * 2 + u;
                const int j = 8 * t + tg;           // word j -> cols (2j, 2j+1)
                unsigned a0 = dq(wr0[j]);
                unsigned a1 = dq(wr8[j]);
                unsigned a2 = dq(wr0[j + 4]);
                unsigned a3 = dq(wr8[j + 4]);
                unsigned bh0 = xhs[w][j * 8 + gid];
                unsigned bh1 = xhs[w][(j + 4) * 8 + gid];
                unsigned bl0 = xls[w][j * 8 + gid];
                unsigned bl1 = xls[w][(j + 4) * 8 + gid];
                mma16816(t0, t1, t2, t3, a0, a1, a2, a3, bh0, bh1);
                mma16816(t0, t1, t2, t3, a0, a1, a2, a3, bl0, bl1);
            }
            float s0 = ssm[w][gid * 5 + blk];
            float s8 = ssm[w][(gid + 8) * 5 + blk];
            acc0 = fmaf(s0, t0, acc0);
            acc1 = fmaf(s0, t1, acc1);
            acc2 = fmaf(s8, t2, acc2);
            acc3 = fmaf(s8, t3, acc3);
        }
    }

    // ── Epilogue: per-warp atomics, no reduction, no CTA barrier.
    const int gr0 = rowbase + gid, gr8 = gr0 + 8;
    atomicAdd(&out[(size_t)(2 * tg)     * OUTF + gr0], acc0);
    atomicAdd(&out[(size_t)(2 * tg + 1) * OUTF + gr0], acc1);
    atomicAdd(&out[(size_t)(2 * tg)     * OUTF + gr8], acc2);
    atomicAdd(&out[(size_t)(2 * tg + 1) * OUTF + gr8], acc3);
}

extern "C" void kernel_launch(void* const* d_in, const int* in_sizes, int n_in,
                              void* d_out, int out_size) {
    const float* x      = (const float*)d_in[0];
    const int*   packed = (const int*)d_in[1];
    const float* scales = (const float*)d_in[2];
    float*       out    = (float*)d_out;

    int nout4 = out_size / 4;
    int naux  = (INF / 2) * 8;
    int nthr  = nout4 > naux ? nout4 : naux;
    prep_zero<<<(nthr + 255) / 256, 256>>>(x, (float4*)out, nout4);

    dim3 grid(NROWT, NKC);                          // (688, 8) = 5504 CTAs, 6/SM
    qlin_kernel<<<grid, 128>>>(packed, scales, out);
}

// round 16
// speedup vs baseline: 1.1045x; 1.1045x over previous
#include <cuda_runtime.h>
#include <cuda_fp16.h>
#include <cstdint>

#define OUTF 11008
#define INF  4096
#define ROWS 64
#define KCTA 256
#define WSTRIDE 132                    // 128 words + 4 pad: banks (4*gid+tg) bijective
#define GRID_X (OUTF / ROWS)           // 172
#define GRID_Y (INF / KCTA)            // 16

// x pre-split to fp16 hi/lo, layout [k2][batch] as half2-in-unsigned.
__device__ __align__(16) unsigned g_XH[(INF / 2) * 8];
__device__ __align__(16) unsigned g_XL[(INF / 2) * 8];

// Fused: zero the output AND split x into fp16 hi/lo slabs. 2 float4/thread zero.
__global__ void prep_zero(const float* __restrict__ x, float4* __restrict__ out4, int nout4) {
    int i = blockIdx.x * blockDim.x + threadIdx.x;
    if (i < (INF / 2) * 8) {
        int k2 = i >> 3, n = i & 7;
        float f0 = x[n * INF + 2 * k2];
        float f1 = x[n * INF + 2 * k2 + 1];
        __half h0 = __float2half_rn(f0), h1 = __float2half_rn(f1);
        __half l0 = __float2half_rn(f0 - __half2float(h0));
        __half l1 = __float2half_rn(f1 - __half2float(h1));
        __half2 H = __halves2half2(h0, h1), L = __halves2half2(l0, l1);
        g_XH[i] = *reinterpret_cast<unsigned*>(&H);
        g_XL[i] = *reinterpret_cast<unsigned*>(&L);
    }
    int z0 = 2 * i, z1 = 2 * i + 1;
    float4 zv = make_float4(0.f, 0.f, 0.f, 0.f);
    if (z0 < nout4) out4[z0] = zv;
    if (z1 < nout4) out4[z1] = zv;
}

// Dequant one packed byte -> half2 (n_lo-8, n_hi-8), exact (Sterbenz).
__device__ __forceinline__ unsigned dq(unsigned v) {
    unsigned t = ((v | (v << 12)) & 0x000F000Fu) | 0x64006400u;  // fp16 (1024+n)
    unsigned c = 0xE408E408u;                                    // half2(-1032)
    __half2 h = __hadd2(*reinterpret_cast<__half2*>(&t),
                        *reinterpret_cast<__half2*>(&c));
    return *reinterpret_cast<unsigned*>(&h);
}

__device__ __forceinline__ void mma16816(float& d0, float& d1, float& d2, float& d3,
                                         unsigned a0, unsigned a1, unsigned a2, unsigned a3,
                                         unsigned b0, unsigned b1) {
    asm volatile(
        "mma.sync.aligned.m16n8k16.row.col.f32.f16.f16.f32 "
        "{%0,%1,%2,%3},{%4,%5,%6,%7},{%8,%9},{%0,%1,%2,%3};"
        : "+f"(d0), "+f"(d1), "+f"(d2), "+f"(d3)
        : "r"(a0), "r"(a1), "r"(a2), "r"(a3), "r"(b0), "r"(b1));
}

__device__ __forceinline__ void cpa16(void* smem, const void* gmem) {
    unsigned s = (unsigned)__cvta_generic_to_shared(smem);
    asm volatile("cp.async.cg.shared.global [%0], [%1], 16;" :: "r"(s), "l"(gmem));
}

__global__ __launch_bounds__(128, 5)
void qlin_kernel(const int*   __restrict__ packed,
                 const float* __restrict__ scales,
                 float*       __restrict__ out) {
    __shared__ __align__(16) unsigned Wsm[ROWS * WSTRIDE];      // 33792 B
    __shared__ __align__(16) unsigned xhs[(KCTA / 2) * 8];      // 4096 B
    __shared__ __align__(16) unsigned xls[(KCTA / 2) * 8];      // 4096 B
    __shared__ __align__(16) float    ssm[ROWS * 9];            // 2304 B

    const int tid  = threadIdx.x;
    const int lane = tid & 31, warp = tid >> 5;
    const int gid  = lane >> 2, tg = lane & 3;
    const int rowbase = blockIdx.x * ROWS;
    const int kbase   = blockIdx.y * KCTA;
    const int kb2     = kbase >> 1;

    const int* pg = packed + (size_t)rowbase * (INF / 2) + kb2;

    // ── Hoisted scales LDG: issue first so its DRAM latency overlaps the
    // async W/x fill drain (stores happen after the loads return, pre-wait).
    float4 sa = make_float4(0, 0, 0, 0), sb = make_float4(0, 0, 0, 0);
    if (tid < ROWS) {
        const float* sg = scales + (size_t)(rowbase + tid) * (INF / 32) + (kbase >> 5);
        sa = *reinterpret_cast<const float4*>(sg);
        sb = *reinterpret_cast<const float4*>(sg + 4);
    }

    // ── Group A: x slabs + W first half (words 0..63 of each row).
    {
        const int4* gh = reinterpret_cast<const int4*>(g_XH + kb2 * 8);
        const int4* gl = reinterpret_cast<const int4*>(g_XL + kb2 * 8);
        cpa16(reinterpret_cast<int4*>(xhs) + tid,       gh + tid);
        cpa16(reinterpret_cast<int4*>(xhs) + 128 + tid, gh + 128 + tid);
        cpa16(reinterpret_cast<int4*>(xls) + tid,       gl + tid);
        cpa16(reinterpret_cast<int4*>(xls) + 128 + tid, gl + 128 + tid);
        #pragma unroll
        for (int p = 0; p < 8; p++) {
            int idx = p * 128 + tid;
            int row = idx >> 4, q = idx & 15;
            cpa16(&Wsm[row * WSTRIDE + q * 4], pg + (size_t)row * (INF / 2) + q * 4);
        }
    }
    asm volatile("cp.async.commit_group;" ::: "memory");
    // ── Group B: W second half (words 64..127).
    {
        #pragma unroll
        for (int p = 0; p < 8; p++) {
            int idx = p * 128 + tid;
            int row = idx >> 4, q = idx & 15;
            cpa16(&Wsm[row * WSTRIDE + 64 + q * 4],
                  pg + (size_t)row * (INF / 2) + 64 + q * 4);
        }
    }
    asm volatile("cp.async.commit_group;" ::: "memory");

    // Scales STS (stride 9: conflict-free on the compute path).
    if (tid < ROWS) {
        float* d = &ssm[tid * 9];
        d[0] = sa.x; d[1] = sa.y; d[2] = sa.z; d[3] = sa.w;
        d[4] = sb.x; d[5] = sb.y; d[6] = sb.z; d[7] = sb.w;
    }

    const int r0 = warp * 16 + gid;                 // rows r0 and r0+8
    const unsigned* wr0 = &Wsm[r0 * WSTRIDE];
    const unsigned* wr8 = wr0 + 8 * WSTRIDE;

    float acc0 = 0.f, acc1 = 0.f, acc2 = 0.f, acc3 = 0.f;

    #pragma unroll
    for (int half = 0; half < 2; half++) {
        if (half == 0)
            asm volatile("cp.async.wait_group 1;" ::: "memory");
        else
            asm volatile("cp.async.wait_group 0;" ::: "memory");
        __syncthreads();

        #pragma unroll
        for (int bb = 0; bb < 4; bb++) {            // q4 block = 32 cols = 2 k-tiles
            const int blk = half * 4 + bb;
            float t0 = 0.f, t1 = 0.f, t2 = 0.f, t3 = 0.f;
            #pragma unroll
            for (int u = 0; u < 2; u++) {
                const int t = blk * 2 + u;
                const int j = 8 * t + tg;           // word j -> cols (2j, 2j+1)
                unsigned a0 = dq(wr0[j]);
                unsigned a1 = dq(wr8[j]);
                unsigned a2 = dq(wr0[j + 4]);
                unsigned a3 = dq(wr8[j + 4]);
                unsigned bh0 = xhs[j * 8 + gid];
                unsigned bh1 = xhs[(j + 4) * 8 + gid];
                unsigned bl0 = xls[j * 8 + gid];
                unsigned bl1 = xls[(j + 4) * 8 + gid];
                mma16816(t0, t1, t2, t3, a0, a1, a2, a3, bh0, bh1);
                mma16816(t0, t1, t2, t3, a0, a1, a2, a3, bl0, bl1);
            }
            float s0 = ssm[r0 * 9 + blk];
            float s8 = ssm[(r0 + 8) * 9 + blk];
            acc0 = fmaf(s0, t0, acc0);
            acc1 = fmaf(s0, t1, acc1);
            acc2 = fmaf(s8, t2, acc2);
            acc3 = fmaf(s8, t3, acc3);
        }
    }

    // ── Epilogue: D frag -> out[batch][row]; 4 atomics/lane, no reduction.
    const int gr0 = rowbase + r0, gr8 = gr0 + 8;
    atomicAdd(&out[(size_t)(2 * tg)     * OUTF + gr0], acc0);
    atomicAdd(&out[(size_t)(2 * tg + 1) * OUTF + gr0], acc1);
    atomicAdd(&out[(size_t)(2 * tg)     * OUTF + gr8], acc2);
    atomicAdd(&out[(size_t)(2 * tg + 1) * OUTF + gr8], acc3);
}

extern "C" void kernel_launch(void* const* d_in, const int* in_sizes, int n_in,
                              void* d_out, int out_size) {
    const float* x      = (const float*)d_in[0];
    const int*   packed = (const int*)d_in[1];
    const float* scales = (const float*)d_in[2];
    float*       out    = (float*)d_out;

    int nout4 = out_size / 4;                       // 22016 float4s
    int naux  = (INF / 2) * 8;                      // 16384 split items
    int nzero = (nout4 + 1) / 2;                    // 2 float4 per thread
    int nthr  = nzero > naux ? nzero : naux;
    prep_zero<<<(nthr + 255) / 256, 256>>>(x, (float4*)out, nout4);

    dim3 grid(GRID_X, GRID_Y);                      // (172, 16) = 2752 CTAs, 5/SM
    qlin_kernel<<<grid, 128>>>(packed, scales, out);
}